// round 17
// baseline (speedup 1.0000x reference)
#include <cuda_runtime.h>
#include <cuda_fp16.h>
#include <math.h>
#include <stdint.h>

#define NV    8192
#define FOUT  64
#define NP    72          // padded N: 64 feats + col64 = denominator + pad
#define JSPL  8
#define JW    (NV / JSPL) // 1024 j per CTA
#define CJ    16          // j chunk staged in smem
#define NCH   (JW / CJ)   // 64 chunks
#define RCTA  256         // rows per CTA (8 warps x 32 rows)

// ------------------------- device scratch (no allocs) -----------------------
__device__ __align__(128) __half g_WhH[NV * NP];   // [j][72]: fp16 Wh, col64=1
__device__ __align__(128) __half g_w1h[NV];        // fp16(-Wh1[i])
__device__ __align__(128) __half g_w2h[NV];        // fp16(Wh2[j])
__device__ __align__(128) __half g_b1h[NV];        // fp16(exp(Wh2[j]))
__device__ __align__(128) __half g_b2h[NV];        // fp16(exp(0.2*Wh2[j]))
__device__ __align__(128) __half g_rh[NV];         // fp16(exp(-0.8*Wh1[i]))
__device__ __align__(128) float  g_pnum[JSPL * NV * NP];

// ------------------------- small PTX helpers --------------------------------
__device__ __forceinline__ uint32_t smem_u32(const void* p) {
    uint32_t a;
    asm("{ .reg .u64 t; cvta.to.shared.u64 t, %1; cvt.u32.u64 %0, t; }" : "=r"(a) : "l"(p));
    return a;
}
__device__ __forceinline__ void cpa16(uint32_t dst, const void* src) {
    asm volatile("cp.async.cg.shared.global [%0], [%1], 16;" :: "r"(dst), "l"(src));
}
#define CP_COMMIT() asm volatile("cp.async.commit_group;")
#define CP_WAIT1()  asm volatile("cp.async.wait_group 1;")

__device__ __forceinline__ void ldsm4t(uint32_t* r, uint32_t addr) {
    asm volatile("ldmatrix.sync.aligned.m8n8.x4.trans.shared.b16 {%0,%1,%2,%3}, [%4];"
                 : "=r"(r[0]), "=r"(r[1]), "=r"(r[2]), "=r"(r[3]) : "r"(addr));
}
__device__ __forceinline__ void ldsm2t(uint32_t* r, uint32_t addr) {
    asm volatile("ldmatrix.sync.aligned.m8n8.x2.trans.shared.b16 {%0,%1}, [%2];"
                 : "=r"(r[0]), "=r"(r[1]) : "r"(addr));
}
__device__ __forceinline__ void mma16816(float* d, const uint32_t* a, const uint32_t* b) {
    asm volatile("mma.sync.aligned.m16n8k16.row.col.f32.f16.f16.f32 "
                 "{%0,%1,%2,%3}, {%4,%5,%6,%7}, {%8,%9}, {%0,%1,%2,%3};"
                 : "+f"(d[0]), "+f"(d[1]), "+f"(d[2]), "+f"(d[3])
                 : "r"(a[0]), "r"(a[1]), "r"(a[2]), "r"(a[3]), "r"(b[0]), "r"(b[1]));
}
__device__ __forceinline__ uint32_t hgt2_mask(uint32_t w2, uint32_t th) {
    __half2 a = *(__half2*)&w2, b = *(__half2*)&th;
    __half2 s = __hgt2(a, b);
    return *(uint32_t*)&s;
}
__device__ __forceinline__ uint32_t hmul2_u(uint32_t a, uint32_t b) {
    __half2 r = __hmul2(*(__half2*)&a, *(__half2*)&b);
    return *(uint32_t*)&r;
}
__device__ __forceinline__ uint32_t hfma2_u(uint32_t a, uint32_t b, uint32_t c) {
    __half2 r = __hfma2(*(__half2*)&a, *(__half2*)&b, *(__half2*)&c);
    return *(uint32_t*)&r;
}

// ---------------------------------------------------------------------------
// Kernel 1 (fused): Wh = x @ W^T  ->  scalars + fp16 WhH table, all in-block
// 64 rows per block, grid 128
// ---------------------------------------------------------------------------
#define KP 68
#define SM_PRE (2 * 128 * KP * 4)
__global__ void __launch_bounds__(256) k_pre(const float* __restrict__ x,
                                             const float* __restrict__ W,
                                             const float* __restrict__ a) {
    extern __shared__ float swh[];
    float* xt = swh;             // [k][row] 128 x 68
    float* wt = swh + 128 * KP;  // [k][col] 128 x 68
    __shared__ float a_s[128];
    const int t = threadIdx.x;
    const int row0 = blockIdx.x * 64;

    if (t < 128) a_s[t] = a[t];

    for (int i4 = t; i4 < 2048; i4 += 256) {
        const int row = i4 >> 5, k4 = (i4 & 31) * 4;
        float4 v = ((const float4*)(x + (size_t)row0 * 128))[i4];
        xt[(k4 + 0) * KP + row] = v.x;
        xt[(k4 + 1) * KP + row] = v.y;
        xt[(k4 + 2) * KP + row] = v.z;
        xt[(k4 + 3) * KP + row] = v.w;
    }
    for (int i4 = t; i4 < 2048; i4 += 256) {
        const int col = i4 >> 5, k4 = (i4 & 31) * 4;
        float4 v = ((const float4*)W)[i4];
        wt[(k4 + 0) * KP + col] = v.x;
        wt[(k4 + 1) * KP + col] = v.y;
        wt[(k4 + 2) * KP + col] = v.z;
        wt[(k4 + 3) * KP + col] = v.w;
    }
    __syncthreads();

    const int ty = t >> 4, tx = t & 15;
    float acc[4][4];
#pragma unroll
    for (int i = 0; i < 4; i++)
#pragma unroll
        for (int j = 0; j < 4; j++) acc[i][j] = 0.f;

#pragma unroll 4
    for (int k = 0; k < 128; k++) {
        const float4 xv = *(const float4*)&xt[k * KP + ty * 4];
        const float4 wv = *(const float4*)&wt[k * KP + tx * 4];
        const float xs[4] = {xv.x, xv.y, xv.z, xv.w};
        const float ws[4] = {wv.x, wv.y, wv.z, wv.w};
#pragma unroll
        for (int i = 0; i < 4; i++)
#pragma unroll
            for (int j = 0; j < 4; j++)
                acc[i][j] = fmaf(xs[i], ws[j], acc[i][j]);
    }
    __syncthreads();                 // everyone done reading xt/wt

    float* whb = swh;                // reuse: [row][65] pitch
#pragma unroll
    for (int i = 0; i < 4; i++) {
        float* dst = &whb[(ty * 4 + i) * 65 + tx * 4];
        dst[0] = acc[i][0]; dst[1] = acc[i][1];
        dst[2] = acc[i][2]; dst[3] = acc[i][3];
    }
    __syncthreads();

    if (t < 64) {
        const int j = row0 + t;
        const float* whr = &whb[t * 65];
        float s1 = 0.f, s2 = 0.f;
#pragma unroll 16
        for (int c = 0; c < 64; c++) {
            s1 = fmaf(whr[c], a_s[c], s1);
            s2 = fmaf(whr[c], a_s[64 + c], s2);
        }
        g_w1h[j] = __float2half(-s1);
        g_w2h[j] = __float2half(s2);
        g_b1h[j] = __float2half(expf(s2));
        g_b2h[j] = __float2half(expf(0.2f * s2));
        g_rh[j]  = __float2half(expf(-0.8f * s1));

        __half2* H = (__half2*)(g_WhH + (size_t)j * NP);
#pragma unroll
        for (int f2 = 0; f2 < 32; f2++)
            H[f2] = __floats2half2_rn(whr[f2 * 2], whr[f2 * 2 + 1]);
        H[32] = __floats2half2_rn(1.0f, 0.f);
#pragma unroll
        for (int f2 = 33; f2 < 36; f2++) H[f2] = __floats2half2_rn(0.f, 0.f);
    }
}

// ---------------------------------------------------------------------------
// Kernel 2: main — 32 rows/warp, 3-stage cp.async pipeline (CJ=16)
// grid = 256 (32 row-blocks x 8 j-splits), 256 threads (8 warps x 32 rows)
// per buffer: adj 256x80=20480 | WhH 16x144=2304 | sc 96  -> 3 buffers
// ---------------------------------------------------------------------------
#define APITCH  80                      // 16 ints (64B) + 16B pad
#define ADJB    20480
#define WHB     2304
#define SCB     96
#define SM_ADJ  0                       // 3 x 20480 = 61440
#define SM_WH   61440                   // 3 x 2304  = 6912
#define SM_SC   68352                   // 3 x 96    = 288
#define SM_MAIN 68640

__global__ void __launch_bounds__(256, 2) k_main(const int* __restrict__ adj) {
    extern __shared__ char sm[];
    const uint32_t smb = smem_u32(sm);
    const int t = threadIdx.x;
    const int w = t >> 5, l = t & 31;
    const int rb = blockIdx.x >> 3;          // row-block 0..31
    const int js = blockIdx.x & 7;           // j-split 0..7
    const int rt0 = rb * RCTA;
    const int jb0 = js * JW;

    const int l2 = (l & 3) * 2;
    const int rl0 = w * 32 + (l >> 2);       // local row stream base
    const int rowA = rt0 + rl0,      rowB = rowA + 8;
    const int rowC = rowA + 16,      rowD = rowA + 24;

    uint32_t th[4], rr[4];
    {
        const int rws[4] = {rowA, rowB, rowC, rowD};
#pragma unroll
        for (int i = 0; i < 4; i++) {
            const uint16_t tv = *(const uint16_t*)&g_w1h[rws[i]];
            const uint16_t rv = *(const uint16_t*)&g_rh[rws[i]];
            th[i] = (uint32_t)tv | ((uint32_t)tv << 16);
            rr[i] = (uint32_t)rv | ((uint32_t)rv << 16);
        }
    }

    float acc1[36], acc2[36];
#pragma unroll
    for (int i = 0; i < 36; i++) { acc1[i] = 0.f; acc2[i] = 0.f; }

    // ---- staging: chunk at global j = jc, into buffer buf (0..2) ----
    auto stage = [&](int buf, int jc) {
        const char* asrc = (const char*)(adj + (size_t)rt0 * NV + jc);
        const uint32_t adst = smb + SM_ADJ + buf * ADJB;
#pragma unroll
        for (int i = 0; i < 4; i++) {
            const int idx = t + i * 256;             // 0..1023 (256 rows x 4 seg)
            const int row = idx >> 2, seg = idx & 3;
            cpa16(adst + row * APITCH + seg * 16,
                  asrc + (size_t)row * (NV * 4) + seg * 16);
        }
        if (t < 144) {                               // WhH: 16 rows x 9 segs
            const int row = t / 9, seg = t - row * 9;
            cpa16(smb + SM_WH + buf * WHB + row * 144 + seg * 16,
                  (const char*)g_WhH + (size_t)(jc + row) * 144 + seg * 16);
        } else if (t < 146) {
            cpa16(smb + SM_SC + buf * SCB + (t - 144) * 16,
                  (const char*)g_w2h + (size_t)jc * 2 + (t - 144) * 16);
        } else if (t < 148) {
            cpa16(smb + SM_SC + buf * SCB + 32 + (t - 146) * 16,
                  (const char*)g_b1h + (size_t)jc * 2 + (t - 146) * 16);
        } else if (t < 150) {
            cpa16(smb + SM_SC + buf * SCB + 64 + (t - 148) * 16,
                  (const char*)g_b2h + (size_t)jc * 2 + (t - 148) * 16);
        }
        CP_COMMIT();
    };

    stage(0, jb0);
    stage(1, jb0 + CJ);

    int buf = 0;
    for (int c = 0; c < NCH; c++) {
        CP_WAIT1();                                  // oldest (chunk c) done
        __syncthreads();
        if (c + 2 < NCH) {
            int nb = buf + 2; if (nb >= 3) nb -= 3;
            stage(nb, jb0 + (c + 2) * CJ);
        } else {
            CP_COMMIT();                             // empty group keeps FIFO math
        }

        const int ao = SM_ADJ + buf * ADJB;
        const uint32_t bw_base = smb + SM_WH + buf * WHB;
        const int sco = SM_SC + buf * SCB;

        {
            const int jbyte = l2 * 4;
            const int2 mA0 = *(const int2*)(sm + ao + (rl0     ) * APITCH + jbyte);
            const int2 mA1 = *(const int2*)(sm + ao + (rl0     ) * APITCH + jbyte + 32);
            const int2 mB0 = *(const int2*)(sm + ao + (rl0 +  8) * APITCH + jbyte);
            const int2 mB1 = *(const int2*)(sm + ao + (rl0 +  8) * APITCH + jbyte + 32);
            const int2 mC0 = *(const int2*)(sm + ao + (rl0 + 16) * APITCH + jbyte);
            const int2 mC1 = *(const int2*)(sm + ao + (rl0 + 16) * APITCH + jbyte + 32);
            const int2 mD0 = *(const int2*)(sm + ao + (rl0 + 24) * APITCH + jbyte);
            const int2 mD1 = *(const int2*)(sm + ao + (rl0 + 24) * APITCH + jbyte + 32);

            const int klo = l2 * 2, khi = klo + 16;
            const uint32_t w2lo = *(const uint32_t*)(sm + sco + klo);
            const uint32_t w2hi = *(const uint32_t*)(sm + sco + khi);
            const uint32_t b1lo = *(const uint32_t*)(sm + sco + 32 + klo);
            const uint32_t b1hi = *(const uint32_t*)(sm + sco + 32 + khi);
            const uint32_t b2lo = *(const uint32_t*)(sm + sco + 64 + klo);
            const uint32_t b2hi = *(const uint32_t*)(sm + sco + 64 + khi);

            uint32_t Q1[4], Q2[4];
            {
                const int2 mlo[4] = {mA0, mB0, mC0, mD0};
                const int2 mhi[4] = {mA1, mB1, mC1, mD1};
                uint32_t q[8];
#pragma unroll
                for (int i = 0; i < 4; i++) {
                    const uint32_t Mlo = (uint32_t)mlo[i].x * 0x3C00u + (uint32_t)mlo[i].y * 0x3C000000u;
                    const uint32_t Mhi = (uint32_t)mhi[i].x * 0x3C00u + (uint32_t)mhi[i].y * 0x3C000000u;
                    const uint32_t Alo = Mlo & hgt2_mask(w2lo, th[i]);
                    const uint32_t Ahi = Mhi & hgt2_mask(w2hi, th[i]);
                    q[i * 2 + 0] = hfma2_u(Alo ^ Mlo, hmul2_u(b2lo, rr[i]), hmul2_u(Alo, b1lo));
                    q[i * 2 + 1] = hfma2_u(Ahi ^ Mhi, hmul2_u(b2hi, rr[i]), hmul2_u(Ahi, b1hi));
                }
                Q1[0] = q[0]; Q1[1] = q[2]; Q1[2] = q[1]; Q1[3] = q[3];
                Q2[0] = q[4]; Q2[1] = q[6]; Q2[2] = q[5]; Q2[3] = q[7];
            }

            const int krow = ((l >> 3) & 1) * 8 + (l & 7);
            const uint32_t cadd = (uint32_t)((l >> 4) * 8) * 2;

#pragma unroll
            for (int nt2 = 0; nt2 < 4; nt2++) {
                uint32_t b[4];
                const uint32_t co = (uint32_t)(nt2 * 16) * 2 + cadd;
                ldsm4t(b, bw_base + (uint32_t)krow * 144 + co);
                mma16816(acc1 + nt2 * 8,     Q1, b);
                mma16816(acc1 + nt2 * 8 + 4, Q1, b + 2);
                mma16816(acc2 + nt2 * 8,     Q2, b);
                mma16816(acc2 + nt2 * 8 + 4, Q2, b + 2);
            }
            {   // denominator column (col64 = 1.0)
                uint32_t b[2];
                const uint32_t a8 = (uint32_t)(l & 15) * 144 + 128;
                ldsm2t(b, bw_base + a8);
                mma16816(acc1 + 32, Q1, b);
                mma16816(acc2 + 32, Q2, b);
            }
        }
        buf++; if (buf >= 3) buf = 0;
    }

    // epilogue: write partials (col64 = denominator)
    float* baseA = g_pnum + ((size_t)js * NV + rowA) * NP;
    float* baseB = g_pnum + ((size_t)js * NV + rowB) * NP;
    float* baseC = g_pnum + ((size_t)js * NV + rowC) * NP;
    float* baseD = g_pnum + ((size_t)js * NV + rowD) * NP;
#pragma unroll
    for (int nt = 0; nt < 9; nt++) {
        const int col = nt * 8 + l2;
        *(float2*)(baseA + col) = make_float2(acc1[nt * 4 + 0], acc1[nt * 4 + 1]);
        *(float2*)(baseB + col) = make_float2(acc1[nt * 4 + 2], acc1[nt * 4 + 3]);
        *(float2*)(baseC + col) = make_float2(acc2[nt * 4 + 0], acc2[nt * 4 + 1]);
        *(float2*)(baseD + col) = make_float2(acc2[nt * 4 + 2], acc2[nt * 4 + 3]);
    }
}

// ---------------------------------------------------------------------------
// Kernel 3: combine j-splits, divide, elu
// ---------------------------------------------------------------------------
__global__ void __launch_bounds__(256) k_final(float* __restrict__ out) {
    const int idx = blockIdx.x * 256 + threadIdx.x;   // 8192*16 slots
    const int row = idx >> 4, f4 = idx & 15;
    float4 num = make_float4(0.f, 0.f, 0.f, 0.f);
    float den = 0.f;
#pragma unroll
    for (int js = 0; js < JSPL; js++) {
        const float* p = g_pnum + ((size_t)js * NV + row) * NP;
        const float4 v = *(const float4*)(p + f4 * 4);
        num.x += v.x; num.y += v.y; num.z += v.z; num.w += v.w;
        den += p[64];
    }
    const float inv = 1.0f / den;
    float4 o;
    float a0 = num.x * inv; o.x = a0 > 0.f ? a0 : expm1f(a0);
    float a1 = num.y * inv; o.y = a1 > 0.f ? a1 : expm1f(a1);
    float a2 = num.z * inv; o.z = a2 > 0.f ? a2 : expm1f(a2);
    float a3 = num.w * inv; o.w = a3 > 0.f ? a3 : expm1f(a3);
    *(float4*)(out + (size_t)row * FOUT + f4 * 4) = o;
}

// ---------------------------------------------------------------------------
extern "C" void kernel_launch(void* const* d_in, const int* in_sizes, int n_in,
                              void* d_out, int out_size) {
    const float* x   = (const float*)d_in[0];
    const int*   adj = (const int*)d_in[1];
    const float* W   = (const float*)d_in[2];
    const float* a   = (const float*)d_in[3];
    float* out = (float*)d_out;

    cudaFuncSetAttribute(k_pre,  cudaFuncAttributeMaxDynamicSharedMemorySize, SM_PRE);
    cudaFuncSetAttribute(k_main, cudaFuncAttributeMaxDynamicSharedMemorySize, SM_MAIN);

    k_pre<<<NV / 64, 256, SM_PRE>>>(x, W, a);
    k_main<<<256, 256, SM_MAIN>>>(adj);
    k_final<<<NV * 16 / 256, 256>>>(out);
}